// round 2
// baseline (speedup 1.0000x reference)
#include <cuda_runtime.h>
#include <cstdint>

// Problem constants (fixed by the dataset): p, q are (B, N, D) fp32 with
// B=64, N=2048, D=4. Output: scalar fp32 chamfer + jet loss.
#define BB       64
#define NN       2048
#define TPB      256
#define IPT      4                    // i-rows per thread (register tile)
#define ROWS_PB  (TPB * IPT)          // 1024 rows per block
#define BPB      (NN / ROWS_PB)       // 2 blocks per batch per direction
#define TILE_J   256
#define NTILES   (NN / TILE_J)        // 8
#define NCHAMFER (2 * BB * BPB)       // 256 chamfer partials
#define JET_OFF  NCHAMFER
#define NPART    (NCHAMFER + BB)      // + 64 jet partials = 320

__device__ float g_part[NPART];

// ---- packed f32x2 helpers (Blackwell: ptxas never auto-emits FFMA2) ----
typedef unsigned long long u64;

__device__ __forceinline__ u64 pack2(float lo, float hi) {
    u64 r;
    asm("mov.b64 %0, {%1, %2};" : "=l"(r) : "f"(lo), "f"(hi));
    return r;
}
__device__ __forceinline__ u64 fma2(u64 a, u64 b, u64 c) {
    u64 r;
    asm("fma.rn.f32x2 %0, %1, %2, %3;" : "=l"(r) : "l"(a), "l"(b), "l"(c));
    return r;
}
__device__ __forceinline__ u64 mul2(u64 a, u64 b) {
    u64 r;
    asm("mul.rn.f32x2 %0, %1, %2;" : "=l"(r) : "l"(a), "l"(b));
    return r;
}
__device__ __forceinline__ void unpack2(u64 v, float& lo, float& hi) {
    asm("mov.b64 {%0, %1}, %2;" : "=f"(lo), "=f"(hi) : "l"(v));
}

// One direction of the chamfer term. blockIdx.z selects (A,B) = (p,q) or (q,p).
// Computes sum over this block's A-rows of [ |a|^2 + min_j(|b_j|^2 - 2 a.b_j) ].
__global__ __launch_bounds__(TPB) void chamfer_kernel(
    const float4* __restrict__ p, const float4* __restrict__ q)
{
    const int b   = blockIdx.y;
    const int z   = blockIdx.z;
    const float4* __restrict__ Arows = (z == 0 ? p : q) + b * NN;
    const float4* __restrict__ Brows = (z == 0 ? q : p) + b * NN;

    __shared__ __align__(16) float sX[TILE_J];
    __shared__ __align__(16) float sY[TILE_J];
    __shared__ __align__(16) float sZ[TILE_J];
    __shared__ __align__(16) float sW[TILE_J];
    __shared__ __align__(16) float sS[TILE_J];

    const int tid = threadIdx.x;
    const u64 NEG2 = pack2(-2.0f, -2.0f);

    // Register-tile IPT rows of A: broadcast each component as an f32x2 pair.
    u64 axx[IPT], ayy[IPT], azz[IPT], aww[IPT];
    float asq[IPT], mmin[IPT];
    #pragma unroll
    for (int k = 0; k < IPT; k++) {
        const int i = blockIdx.x * ROWS_PB + k * TPB + tid;
        const float4 a = Arows[i];
        axx[k] = pack2(a.x, a.x);
        ayy[k] = pack2(a.y, a.y);
        azz[k] = pack2(a.z, a.z);
        aww[k] = pack2(a.w, a.w);
        asq[k] = a.x * a.x + a.y * a.y + a.z * a.z + a.w * a.w;
        mmin[k] = __int_as_float(0x7f800000);  // +inf
    }

    for (int t = 0; t < NTILES; t++) {
        const float4 qv = Brows[t * TILE_J + tid];
        __syncthreads();                       // previous tile fully consumed
        sX[tid] = qv.x;
        sY[tid] = qv.y;
        sZ[tid] = qv.z;
        sW[tid] = qv.w;
        sS[tid] = qv.x * qv.x + qv.y * qv.y + qv.z * qv.z + qv.w * qv.w;
        __syncthreads();

        #pragma unroll 4
        for (int jj = 0; jj < TILE_J; jj += 2) {
            // SoA layout -> one aligned LDS.64 per component gives a ready
            // f32x2 pair for two q-points (warp-broadcast, conflict-free).
            const u64 xp  = *reinterpret_cast<const u64*>(&sX[jj]);
            const u64 yp  = *reinterpret_cast<const u64*>(&sY[jj]);
            const u64 zp  = *reinterpret_cast<const u64*>(&sZ[jj]);
            const u64 wp  = *reinterpret_cast<const u64*>(&sW[jj]);
            const u64 sqp = *reinterpret_cast<const u64*>(&sS[jj]);
            #pragma unroll
            for (int k = 0; k < IPT; k++) {
                u64 s = fma2(axx[k], xp,
                         fma2(ayy[k], yp,
                          fma2(azz[k], zp,
                           mul2(aww[k], wp))));
                u64 u = fma2(s, NEG2, sqp);    // |b|^2 - 2 a.b  (two j's)
                float u0, u1;
                unpack2(u, u0, u1);
                mmin[k] = fminf(mmin[k], u0);
                mmin[k] = fminf(mmin[k], u1);
            }
        }
    }

    float local = 0.0f;
    #pragma unroll
    for (int k = 0; k < IPT; k++) local += asq[k] + mmin[k];

    // Deterministic block tree-reduction (reuse sX after sync).
    __syncthreads();
    sX[tid] = local;
    __syncthreads();
    #pragma unroll
    for (int off = TPB / 2; off > 0; off >>= 1) {
        if (tid < off) sX[tid] += sX[tid + off];
        __syncthreads();
    }
    if (tid == 0)
        g_part[z * (BB * BPB) + b * BPB + blockIdx.x] = sX[0];
}

// Jet term: per batch, |sum_i p_i - sum_i q_i|^2.
__global__ __launch_bounds__(TPB) void jet_kernel(
    const float4* __restrict__ p, const float4* __restrict__ q)
{
    const int b = blockIdx.x;
    const int tid = threadIdx.x;
    float dx = 0.f, dy = 0.f, dz = 0.f, dw = 0.f;
    for (int i = tid; i < NN; i += TPB) {
        const float4 a = p[b * NN + i];
        const float4 c = q[b * NN + i];
        dx += a.x - c.x;
        dy += a.y - c.y;
        dz += a.z - c.z;
        dw += a.w - c.w;
    }
    __shared__ float4 sh[TPB];
    sh[tid] = make_float4(dx, dy, dz, dw);
    __syncthreads();
    #pragma unroll
    for (int off = TPB / 2; off > 0; off >>= 1) {
        if (tid < off) {
            sh[tid].x += sh[tid + off].x;
            sh[tid].y += sh[tid + off].y;
            sh[tid].z += sh[tid + off].z;
            sh[tid].w += sh[tid + off].w;
        }
        __syncthreads();
    }
    if (tid == 0) {
        const float4 d = sh[0];
        g_part[JET_OFF + b] = d.x * d.x + d.y * d.y + d.z * d.z + d.w * d.w;
    }
}

// Deterministic final reduction of all partials into the scalar output.
__global__ __launch_bounds__(TPB) void finalize_kernel(float* __restrict__ out)
{
    const int tid = threadIdx.x;
    float v = 0.0f;
    for (int idx = tid; idx < NPART; idx += TPB) v += g_part[idx];
    __shared__ float sh[TPB];
    sh[tid] = v;
    __syncthreads();
    #pragma unroll
    for (int off = TPB / 2; off > 0; off >>= 1) {
        if (tid < off) sh[tid] += sh[tid + off];
        __syncthreads();
    }
    if (tid == 0) out[0] = sh[0];
}

extern "C" void kernel_launch(void* const* d_in, const int* in_sizes, int n_in,
                              void* d_out, int out_size)
{
    const float4* p = (const float4*)d_in[0];
    const float4* q = (const float4*)d_in[1];
    float* out = (float*)d_out;

    dim3 grid(BPB, BB, 2);               // 2*64*2 = 256 blocks, one wave
    chamfer_kernel<<<grid, TPB>>>(p, q);
    jet_kernel<<<BB, TPB>>>(p, q);
    finalize_kernel<<<1, TPB>>>(out);
}

// round 3
// speedup vs baseline: 1.0025x; 1.0025x over previous
#include <cuda_runtime.h>

// p, q: (B=64, N=2048, D=4) fp32. Output: scalar chamfer + jet loss.
#define BB       64
#define NN       2048
#define TPB      64                   // 2 warps per block
#define IPT      4                    // i-rows per thread (register tile)
#define ROWS_PB  (TPB * IPT)          // 256 rows per block
#define XB       (NN / ROWS_PB)       // 8 x-panels -> 2*64*8 = 1024 blocks
#define TILE_J   512
#define NTILES   (NN / TILE_J)        // 4
#define GSTRIDE  12                   // floats per j-pair group (48B, 16B-aligned)
#define NCHAM    (2 * BB * XB)        // 1024 chamfer partials

__device__ float  g_cham[NCHAM];
__device__ float4 g_jet[NCHAM];       // per-block 4-momentum sums of A rows

typedef unsigned long long u64;

__device__ __forceinline__ u64 pack2(float lo, float hi) {
    u64 r; asm("mov.b64 %0, {%1, %2};" : "=l"(r) : "f"(lo), "f"(hi)); return r;
}
__device__ __forceinline__ u64 fma2(u64 a, u64 b, u64 c) {
    u64 r; asm("fma.rn.f32x2 %0, %1, %2, %3;" : "=l"(r) : "l"(a), "l"(b), "l"(c)); return r;
}
__device__ __forceinline__ void unpack2(u64 v, float& lo, float& hi) {
    asm("mov.b64 {%0, %1}, %2;" : "=f"(lo), "=f"(hi) : "l"(v));
}

// One direction of the chamfer term; blockIdx.z selects (A,B) = (p,q) or (q,p).
// Per A-row i: asq_i + min_j( |b_j|^2 - 2 a_i.b_j ). Also accumulates sum of
// this block's A rows for the fused jet term.
__global__ __launch_bounds__(TPB) void chamfer_kernel(
    const float4* __restrict__ p, const float4* __restrict__ q)
{
    const int b = blockIdx.y, z = blockIdx.z, xb = blockIdx.x, tid = threadIdx.x;
    const float4* __restrict__ Arows = (z == 0 ? p : q) + b * NN;
    const float4* __restrict__ Brows = (z == 0 ? q : p) + b * NN;

    // Pair-group tile: for j-pair g: [x0 x1 y0 y1 z0 z1 w0 w1 s0 s1 pad pad]
    __shared__ __align__(16) float sT[(TILE_J / 2) * GSTRIDE];   // 12 KB
    __shared__ float4 sJet[TPB];

    // Register-tile IPT rows of A, pre-multiplied by -2 (folds the -2*cross
    // combine into the dot chain seeded with |b|^2: 4 FFMA2 per 2 pairs).
    u64 ax[IPT], ay[IPT], az[IPT], aw[IPT];
    float asq[IPT], mlo[IPT], mhi[IPT];
    float jx = 0.f, jy = 0.f, jz = 0.f, jw = 0.f;
    #pragma unroll
    for (int k = 0; k < IPT; k++) {
        const int i = xb * ROWS_PB + k * TPB + tid;
        const float4 a = Arows[i];
        jx += a.x; jy += a.y; jz += a.z; jw += a.w;
        ax[k] = pack2(-2.f * a.x, -2.f * a.x);
        ay[k] = pack2(-2.f * a.y, -2.f * a.y);
        az[k] = pack2(-2.f * a.z, -2.f * a.z);
        aw[k] = pack2(-2.f * a.w, -2.f * a.w);
        asq[k] = a.x * a.x + a.y * a.y + a.z * a.z + a.w * a.w;
        mlo[k] = __int_as_float(0x7f800000);
        mhi[k] = __int_as_float(0x7f800000);
    }

    for (int t = 0; t < NTILES; t++) {
        __syncthreads();                       // previous tile fully consumed
        for (int jl = tid; jl < TILE_J; jl += TPB) {
            const float4 v = Brows[t * TILE_J + jl];
            float* gp = &sT[(jl >> 1) * GSTRIDE + (jl & 1)];
            gp[0] = v.x; gp[2] = v.y; gp[4] = v.z; gp[6] = v.w;
            gp[8] = v.x * v.x + v.y * v.y + v.z * v.z + v.w * v.w;
        }
        __syncthreads();

        #pragma unroll 4
        for (int g = 0; g < TILE_J / 2; g++) {
            const float* gp = &sT[g * GSTRIDE];
            const ulonglong2 xy = *reinterpret_cast<const ulonglong2*>(gp);     // LDS.128
            const ulonglong2 zw = *reinterpret_cast<const ulonglong2*>(gp + 4); // LDS.128
            const u64 sq = *reinterpret_cast<const u64*>(gp + 8);               // LDS.64
            #pragma unroll
            for (int k = 0; k < IPT; k++) {
                u64 u = fma2(ax[k], xy.x,
                         fma2(ay[k], xy.y,
                          fma2(az[k], zw.x,
                           fma2(aw[k], zw.y, sq))));   // |b|^2 - 2 a.b (two j's)
                float u0, u1;
                unpack2(u, u0, u1);
                mlo[k] = fminf(mlo[k], u0);            // independent accumulators:
                mhi[k] = fminf(mhi[k], u1);            // no serial FMNMX dependency
            }
        }
    }

    float local = 0.0f;
    #pragma unroll
    for (int k = 0; k < IPT; k++) local += asq[k] + fminf(mlo[k], mhi[k]);

    // Deterministic block reductions: chamfer scalar (reuse sT) + jet float4.
    __syncthreads();
    float* sC = sT;
    sC[tid] = local;
    sJet[tid] = make_float4(jx, jy, jz, jw);
    __syncthreads();
    #pragma unroll
    for (int off = TPB / 2; off > 0; off >>= 1) {
        if (tid < off) {
            sC[tid] += sC[tid + off];
            sJet[tid].x += sJet[tid + off].x;
            sJet[tid].y += sJet[tid + off].y;
            sJet[tid].z += sJet[tid + off].z;
            sJet[tid].w += sJet[tid + off].w;
        }
        __syncthreads();
    }
    if (tid == 0) {
        const int slot = (z * BB + b) * XB + xb;
        g_cham[slot] = sC[0];
        g_jet[slot]  = sJet[0];
    }
}

// Final deterministic reduction: chamfer partials + per-batch jet term.
__global__ __launch_bounds__(256) void finalize_kernel(float* __restrict__ out)
{
    const int tid = threadIdx.x;
    float v = 0.0f;
    for (int i = tid; i < NCHAM; i += 256) v += g_cham[i];
    if (tid < BB) {
        float dx = 0.f, dy = 0.f, dz = 0.f, dw = 0.f;
        #pragma unroll
        for (int x = 0; x < XB; x++) {
            const float4 sp = g_jet[(0 * BB + tid) * XB + x];   // sum of p rows
            const float4 sq = g_jet[(1 * BB + tid) * XB + x];   // sum of q rows
            dx += sp.x - sq.x; dy += sp.y - sq.y;
            dz += sp.z - sq.z; dw += sp.w - sq.w;
        }
        v += dx * dx + dy * dy + dz * dz + dw * dw;
    }
    __shared__ float sh[256];
    sh[tid] = v;
    __syncthreads();
    #pragma unroll
    for (int off = 128; off > 0; off >>= 1) {
        if (tid < off) sh[tid] += sh[tid + off];
        __syncthreads();
    }
    if (tid == 0) out[0] = sh[0];
}

extern "C" void kernel_launch(void* const* d_in, const int* in_sizes, int n_in,
                              void* d_out, int out_size)
{
    const float4* p = (const float4*)d_in[0];
    const float4* q = (const float4*)d_in[1];
    float* out = (float*)d_out;

    dim3 grid(XB, BB, 2);                 // 1024 blocks, ~1% wave tail
    chamfer_kernel<<<grid, TPB>>>(p, q);
    finalize_kernel<<<1, 256>>>(out);
}

// round 4
// speedup vs baseline: 1.0371x; 1.0345x over previous
#include <cuda_runtime.h>

// p, q: (B=64, N=2048, D=4) fp32. Output: scalar chamfer + jet loss.
#define BB       64
#define NN       2048
#define TPB      128                  // 4 warps per block
#define IPT      2                    // i-rows per thread: 4096 warps total,
                                      // ~6.9 warps/SMSP -> latency well hidden
#define ROWS_PB  (TPB * IPT)          // 256 rows per block
#define XB       (NN / ROWS_PB)       // 8 x-panels -> 2*64*8 = 1024 blocks
#define TILE_J   512
#define NTILES   (NN / TILE_J)        // 4
#define GSTRIDE  12                   // floats per j-pair group (48B, 16B-aligned)
#define NCHAM    (2 * BB * XB)        // 1024 chamfer partials

__device__ float  g_cham[NCHAM];
__device__ float4 g_jet[NCHAM];       // per-block 4-momentum sums of A rows

typedef unsigned long long u64;

__device__ __forceinline__ u64 pack2(float lo, float hi) {
    u64 r; asm("mov.b64 %0, {%1, %2};" : "=l"(r) : "f"(lo), "f"(hi)); return r;
}
__device__ __forceinline__ u64 fma2(u64 a, u64 b, u64 c) {
    u64 r; asm("fma.rn.f32x2 %0, %1, %2, %3;" : "=l"(r) : "l"(a), "l"(b), "l"(c)); return r;
}
__device__ __forceinline__ void unpack2(u64 v, float& lo, float& hi) {
    asm("mov.b64 {%0, %1}, %2;" : "=f"(lo), "=f"(hi) : "l"(v));
}

// One direction of the chamfer term; blockIdx.z selects (A,B) = (p,q) or (q,p).
// Per A-row i: asq_i + min_j( |b_j|^2 - 2 a_i.b_j ). Also accumulates sum of
// this block's A rows for the fused jet term.
__global__ __launch_bounds__(TPB) void chamfer_kernel(
    const float4* __restrict__ p, const float4* __restrict__ q)
{
    const int b = blockIdx.y, z = blockIdx.z, xb = blockIdx.x, tid = threadIdx.x;
    const float4* __restrict__ Arows = (z == 0 ? p : q) + b * NN;
    const float4* __restrict__ Brows = (z == 0 ? q : p) + b * NN;

    // Pair-group tile: for j-pair g: [x0 x1 y0 y1 z0 z1 w0 w1 s0 s1 pad pad]
    __shared__ __align__(16) float sT[(TILE_J / 2) * GSTRIDE];   // 12 KB
    __shared__ float4 sJet[TPB];

    // Register-tile IPT rows of A, pre-multiplied by -2 (folds the -2*cross
    // combine into the dot chain seeded with |b|^2: 4 FFMA2 per 2 pairs).
    u64 ax[IPT], ay[IPT], az[IPT], aw[IPT];
    float asq[IPT], mlo[IPT], mhi[IPT];
    float jx = 0.f, jy = 0.f, jz = 0.f, jw = 0.f;
    #pragma unroll
    for (int k = 0; k < IPT; k++) {
        const int i = xb * ROWS_PB + k * TPB + tid;
        const float4 a = Arows[i];
        jx += a.x; jy += a.y; jz += a.z; jw += a.w;
        ax[k] = pack2(-2.f * a.x, -2.f * a.x);
        ay[k] = pack2(-2.f * a.y, -2.f * a.y);
        az[k] = pack2(-2.f * a.z, -2.f * a.z);
        aw[k] = pack2(-2.f * a.w, -2.f * a.w);
        asq[k] = a.x * a.x + a.y * a.y + a.z * a.z + a.w * a.w;
        mlo[k] = __int_as_float(0x7f800000);
        mhi[k] = __int_as_float(0x7f800000);
    }

    for (int t = 0; t < NTILES; t++) {
        __syncthreads();                       // previous tile fully consumed
        #pragma unroll
        for (int jl = tid; jl < TILE_J; jl += TPB) {
            const float4 v = Brows[t * TILE_J + jl];
            float* gp = &sT[(jl >> 1) * GSTRIDE + (jl & 1)];
            gp[0] = v.x; gp[2] = v.y; gp[4] = v.z; gp[6] = v.w;
            gp[8] = v.x * v.x + v.y * v.y + v.z * v.z + v.w * v.w;
        }
        __syncthreads();

        #pragma unroll 8
        for (int g = 0; g < TILE_J / 2; g++) {
            const float* gp = &sT[g * GSTRIDE];
            const ulonglong2 xy = *reinterpret_cast<const ulonglong2*>(gp);     // LDS.128
            const ulonglong2 zw = *reinterpret_cast<const ulonglong2*>(gp + 4); // LDS.128
            const u64 sq = *reinterpret_cast<const u64*>(gp + 8);               // LDS.64
            #pragma unroll
            for (int k = 0; k < IPT; k++) {
                u64 u = fma2(ax[k], xy.x,
                         fma2(ay[k], xy.y,
                          fma2(az[k], zw.x,
                           fma2(aw[k], zw.y, sq))));   // |b|^2 - 2 a.b (two j's)
                float u0, u1;
                unpack2(u, u0, u1);
                mlo[k] = fminf(mlo[k], u0);            // independent accumulators:
                mhi[k] = fminf(mhi[k], u1);            // no serial FMNMX dependency
            }
        }
    }

    float local = 0.0f;
    #pragma unroll
    for (int k = 0; k < IPT; k++) local += asq[k] + fminf(mlo[k], mhi[k]);

    // Deterministic block reductions: chamfer scalar (reuse sT) + jet float4.
    __syncthreads();
    float* sC = sT;
    sC[tid] = local;
    sJet[tid] = make_float4(jx, jy, jz, jw);
    __syncthreads();
    #pragma unroll
    for (int off = TPB / 2; off > 0; off >>= 1) {
        if (tid < off) {
            sC[tid] += sC[tid + off];
            sJet[tid].x += sJet[tid + off].x;
            sJet[tid].y += sJet[tid + off].y;
            sJet[tid].z += sJet[tid + off].z;
            sJet[tid].w += sJet[tid + off].w;
        }
        __syncthreads();
    }
    if (tid == 0) {
        const int slot = (z * BB + b) * XB + xb;
        g_cham[slot] = sC[0];
        g_jet[slot]  = sJet[0];
    }
}

// Final deterministic reduction: chamfer partials + per-batch jet term.
__global__ __launch_bounds__(256) void finalize_kernel(float* __restrict__ out)
{
    const int tid = threadIdx.x;
    float v = 0.0f;
    for (int i = tid; i < NCHAM; i += 256) v += g_cham[i];
    if (tid < BB) {
        float dx = 0.f, dy = 0.f, dz = 0.f, dw = 0.f;
        #pragma unroll
        for (int x = 0; x < XB; x++) {
            const float4 sp = g_jet[(0 * BB + tid) * XB + x];   // sum of p rows
            const float4 sq = g_jet[(1 * BB + tid) * XB + x];   // sum of q rows
            dx += sp.x - sq.x; dy += sp.y - sq.y;
            dz += sp.z - sq.z; dw += sp.w - sq.w;
        }
        v += dx * dx + dy * dy + dz * dz + dw * dw;
    }
    __shared__ float sh[256];
    sh[tid] = v;
    __syncthreads();
    #pragma unroll
    for (int off = 128; off > 0; off >>= 1) {
        if (tid < off) sh[tid] += sh[tid + off];
        __syncthreads();
    }
    if (tid == 0) out[0] = sh[0];
}

extern "C" void kernel_launch(void* const* d_in, const int* in_sizes, int n_in,
                              void* d_out, int out_size)
{
    const float4* p = (const float4*)d_in[0];
    const float4* q = (const float4*)d_in[1];
    float* out = (float*)d_out;

    dim3 grid(XB, BB, 2);                 // 1024 blocks of 4 warps
    chamfer_kernel<<<grid, TPB>>>(p, q);
    finalize_kernel<<<1, 256>>>(out);
}

// round 5
// speedup vs baseline: 1.2160x; 1.1726x over previous
#include <cuda_runtime.h>
#include <cstdint>

// p, q: (B=64, N=2048, D=4) fp32 -> scalar chamfer + jet loss.
// Tensor-core path: cross = p.q^T via mma.sync m16n8k8 tf32 with hi/lo split
// (2 MMAs give the exact full product), register-resident D fragments,
// row-min (p side) and col-min (q side) reduced straight off the fragments.
#define BB       64
#define NN       2048
#define PANELS   2
#define PROWS    (NN / PANELS)           // 1024 p-rows per block
#define TPB      512
#define NWARP    (TPB / 32)              // 16
#define ITILES   (PROWS / 16)            // 64 i-tiles (m16)
#define JT_PER_W ((NN / 8) / NWARP)      // 16 j-tiles (n8) per warp
#define NBLK     (BB * PANELS)           // 128 blocks
#define FINF     __int_as_float(0x7f800000)

__device__ float  g_colmin[NBLK * NN];   // per-panel col-min partials (q side)
__device__ float  g_cham[NBLK];          // per-block row-side sums (p side)
__device__ float4 g_jetp[NBLK];          // per-block p 4-momentum sums
__device__ float4 g_jetq[BB];            // per-batch q 4-momentum sums
__device__ float  g_batch[BB];

struct Smem {
    unsigned uA[PROWS * 8];              // p panel: [h0 l0 h1 l1 h2 l2 h3 l3] tf32
    unsigned uB[NN * 8];                 // q full:  same interleave
    float    psq[PROWS];
    float    qsq[NN];
    float    rowPart[NWARP][PROWS];      // per-warp row-min partials (+ scratch)
};
#define SMEM_BYTES ((int)sizeof(Smem))

__device__ __forceinline__ unsigned cvt_tf32(float x) {
    unsigned r; asm("cvt.rna.tf32.f32 %0, %1;" : "=r"(r) : "f"(x)); return r;
}
__device__ __forceinline__ void split_store(unsigned* dst, float v) {
    unsigned h = cvt_tf32(v);
    dst[0] = h;
    dst[1] = cvt_tf32(v - __uint_as_float(h));
}
__device__ __forceinline__ void mma_tf32(
    float& d0, float& d1, float& d2, float& d3,
    unsigned a0, unsigned a1, unsigned a2, unsigned a3,
    unsigned b0, unsigned b1,
    float c0, float c1, float c2, float c3)
{
    asm volatile(
        "mma.sync.aligned.m16n8k8.row.col.f32.tf32.tf32.f32 "
        "{%0,%1,%2,%3}, {%4,%5,%6,%7}, {%8,%9}, {%10,%11,%12,%13};\n"
        : "=f"(d0), "=f"(d1), "=f"(d2), "=f"(d3)
        : "r"(a0), "r"(a1), "r"(a2), "r"(a3), "r"(b0), "r"(b1),
          "f"(c0), "f"(c1), "f"(c2), "f"(c3));
}

__global__ __launch_bounds__(TPB, 1) void chamfer_mma(
    const float4* __restrict__ p, const float4* __restrict__ q)
{
    extern __shared__ __align__(16) unsigned char smem_raw[];
    Smem& s = *reinterpret_cast<Smem*>(smem_raw);
    const int b = blockIdx.y, h = blockIdx.x, tid = threadIdx.x;
    const int w = tid >> 5, lane = tid & 31, g = lane >> 2, t4 = lane & 3;

    // ---- stage: tf32 hi/lo split of p panel + full q; psq/qsq; jet sums ----
    float jpx = 0.f, jpy = 0.f, jpz = 0.f, jpw = 0.f;
    float jqx = 0.f, jqy = 0.f, jqz = 0.f, jqw = 0.f;
    for (int r = tid; r < PROWS; r += TPB) {
        const float4 a = p[b * NN + h * PROWS + r];
        jpx += a.x; jpy += a.y; jpz += a.z; jpw += a.w;
        s.psq[r] = a.x * a.x + a.y * a.y + a.z * a.z + a.w * a.w;
        unsigned* d = &s.uA[r * 8];
        split_store(d + 0, a.x); split_store(d + 2, a.y);
        split_store(d + 4, a.z); split_store(d + 6, a.w);
    }
    for (int n = tid; n < NN; n += TPB) {
        const float4 v = q[b * NN + n];
        jqx += v.x; jqy += v.y; jqz += v.z; jqw += v.w;
        s.qsq[n] = v.x * v.x + v.y * v.y + v.z * v.z + v.w * v.w;
        unsigned* d = &s.uB[n * 8];
        split_store(d + 0, v.x); split_store(d + 2, v.y);
        split_store(d + 4, v.z); split_store(d + 6, v.w);
    }
    // jet block-reduction in rowPart scratch (before its +inf init)
    __syncthreads();
    float4* scr = reinterpret_cast<float4*>(&s.rowPart[0][0]);
    scr[tid]       = make_float4(jpx, jpy, jpz, jpw);
    scr[TPB + tid] = make_float4(jqx, jqy, jqz, jqw);
    __syncthreads();
    #pragma unroll
    for (int off = TPB / 2; off > 0; off >>= 1) {
        if (tid < off) {
            float4 a = scr[tid], c = scr[tid + off];
            scr[tid] = make_float4(a.x + c.x, a.y + c.y, a.z + c.z, a.w + c.w);
            float4 e = scr[TPB + tid], f = scr[TPB + tid + off];
            scr[TPB + tid] = make_float4(e.x + f.x, e.y + f.y, e.z + f.z, e.w + f.w);
        }
        __syncthreads();
    }
    if (tid == 0) {
        g_jetp[b * PANELS + h] = scr[0];
        if (h == 0) g_jetq[b] = scr[TPB];
    }
    __syncthreads();
    for (int i = tid; i < NWARP * PROWS; i += TPB)
        (&s.rowPart[0][0])[i] = FINF;
    __syncthreads();

    // ---- main sweep: warp w owns j-tiles [w*16, w*16+16), all i-tiles ----
    float colA[JT_PER_W], colB[JT_PER_W];
    #pragma unroll
    for (int jj = 0; jj < JT_PER_W; jj++) { colA[jj] = FINF; colB[jj] = FINF; }

    for (int it = 0; it < ITILES; ++it) {
        const int r = it * 16 + g;
        const uint2 aL = *reinterpret_cast<const uint2*>(&s.uA[r * 8 + 2 * t4]);       // (a0,a2)
        const uint2 aH = *reinterpret_cast<const uint2*>(&s.uA[(r + 8) * 8 + 2 * t4]); // (a1,a3)
        const float psq0 = s.psq[r], psq1 = s.psq[r + 8];
        float rA0 = FINF, rB0 = FINF, rA1 = FINF, rB1 = FINF;

        #pragma unroll
        for (int jj = 0; jj < JT_PER_W; ++jj) {
            const int n8 = (w * JT_PER_W + jj) * 8;
            const uint2  bb = *reinterpret_cast<const uint2*>(&s.uB[(n8 + g) * 8 + 2 * t4]); // (b0,b1)
            const float2 qq = *reinterpret_cast<const float2*>(&s.qsq[n8 + 2 * t4]);
            float d0, d1, d2, d3;
            // hi*hi + lo*lo, then hi*lo + lo*hi  -> exact fp32-split product
            mma_tf32(d0, d1, d2, d3, aL.x, aH.x, aL.y, aH.y, bb.x, bb.y,
                     0.f, 0.f, 0.f, 0.f);
            mma_tf32(d0, d1, d2, d3, aL.x, aH.x, aL.y, aH.y, bb.y, bb.x,
                     d0, d1, d2, d3);
            // row side: u = qsq_j - 2c ; col side: v = psq_i - 2c
            const float u0 = fmaf(-2.f, d0, qq.x), u1 = fmaf(-2.f, d1, qq.y);
            const float u2 = fmaf(-2.f, d2, qq.x), u3 = fmaf(-2.f, d3, qq.y);
            rA0 = fminf(rA0, u0); rB0 = fminf(rB0, u1);
            rA1 = fminf(rA1, u2); rB1 = fminf(rB1, u3);
            const float v0 = fmaf(-2.f, d0, psq0), v1 = fmaf(-2.f, d1, psq0);
            const float v2 = fmaf(-2.f, d2, psq1), v3 = fmaf(-2.f, d3, psq1);
            colA[jj] = fminf(fminf(colA[jj], v0), v2);
            colB[jj] = fminf(fminf(colB[jj], v1), v3);
        }
        // fold this i-tile's row mins: reduce over tid4 lanes, RMW warp slice
        float r0 = fminf(rA0, rB0), r1 = fminf(rA1, rB1);
        r0 = fminf(r0, __shfl_xor_sync(0xffffffffu, r0, 1));
        r0 = fminf(r0, __shfl_xor_sync(0xffffffffu, r0, 2));
        r1 = fminf(r1, __shfl_xor_sync(0xffffffffu, r1, 1));
        r1 = fminf(r1, __shfl_xor_sync(0xffffffffu, r1, 2));
        if (t4 == 0) {
            s.rowPart[w][r]     = fminf(s.rowPart[w][r],     r0);
            s.rowPart[w][r + 8] = fminf(s.rowPart[w][r + 8], r1);
        }
    }

    // ---- col-min writeout (warp-private cols; reduce over groupID lanes) ----
    #pragma unroll
    for (int jj = 0; jj < JT_PER_W; ++jj) {
        float c0 = colA[jj], c1 = colB[jj];
        c0 = fminf(c0, __shfl_xor_sync(0xffffffffu, c0, 4));
        c0 = fminf(c0, __shfl_xor_sync(0xffffffffu, c0, 8));
        c0 = fminf(c0, __shfl_xor_sync(0xffffffffu, c0, 16));
        c1 = fminf(c1, __shfl_xor_sync(0xffffffffu, c1, 4));
        c1 = fminf(c1, __shfl_xor_sync(0xffffffffu, c1, 8));
        c1 = fminf(c1, __shfl_xor_sync(0xffffffffu, c1, 16));
        if (g == 0) {
            const int col = (w * JT_PER_W + jj) * 8 + 2 * t4;
            g_colmin[(b * PANELS + h) * NN + col]     = c0;
            g_colmin[(b * PANELS + h) * NN + col + 1] = c1;
        }
    }
    __syncthreads();

    // ---- row side: combine 16 warp partials, add psq, block sum ----
    float local = 0.f;
    for (int r = tid; r < PROWS; r += TPB) {
        float m = s.rowPart[0][r];
        #pragma unroll
        for (int ww = 1; ww < NWARP; ww++) m = fminf(m, s.rowPart[ww][r]);
        local += s.psq[r] + m;
    }
    __syncthreads();
    float* red = &s.rowPart[0][0];
    red[tid] = local;
    __syncthreads();
    #pragma unroll
    for (int off = TPB / 2; off > 0; off >>= 1) {
        if (tid < off) red[tid] += red[tid + off];
        __syncthreads();
    }
    if (tid == 0) g_cham[b * PANELS + h] = red[0];
}

// Per batch: col-side sum over j (min of the 2 panel partials + qsq) + jet.
__global__ __launch_bounds__(256) void finalize1(const float4* __restrict__ q)
{
    const int b = blockIdx.x, tid = threadIdx.x;
    float local = 0.f;
    for (int j = tid; j < NN; j += 256) {
        const float4 v = q[b * NN + j];
        const float qsq = v.x * v.x + v.y * v.y + v.z * v.z + v.w * v.w;
        const float m = fminf(g_colmin[(b * 2 + 0) * NN + j],
                              g_colmin[(b * 2 + 1) * NN + j]);
        local += qsq + m;
    }
    if (tid == 0) {
        const float4 s0 = g_jetp[b * 2], s1 = g_jetp[b * 2 + 1], sq = g_jetq[b];
        const float dx = s0.x + s1.x - sq.x, dy = s0.y + s1.y - sq.y;
        const float dz = s0.z + s1.z - sq.z, dw = s0.w + s1.w - sq.w;
        local += dx * dx + dy * dy + dz * dz + dw * dw;
    }
    __shared__ float sh[256];
    sh[tid] = local;
    __syncthreads();
    #pragma unroll
    for (int off = 128; off > 0; off >>= 1) {
        if (tid < off) sh[tid] += sh[tid + off];
        __syncthreads();
    }
    if (tid == 0) g_batch[b] = sh[0];
}

__global__ __launch_bounds__(128) void finalize2(float* __restrict__ out)
{
    const int tid = threadIdx.x;
    float v = 0.f;
    for (int i = tid; i < BB; i += 128)   v += g_batch[i];
    for (int i = tid; i < NBLK; i += 128) v += g_cham[i];
    __shared__ float sh[128];
    sh[tid] = v;
    __syncthreads();
    #pragma unroll
    for (int off = 64; off > 0; off >>= 1) {
        if (tid < off) sh[tid] += sh[tid + off];
        __syncthreads();
    }
    if (tid == 0) out[0] = sh[0];
}

extern "C" void kernel_launch(void* const* d_in, const int* in_sizes, int n_in,
                              void* d_out, int out_size)
{
    const float4* p = (const float4*)d_in[0];
    const float4* q = (const float4*)d_in[1];
    float* out = (float*)d_out;

    cudaFuncSetAttribute(chamfer_mma,
                         cudaFuncAttributeMaxDynamicSharedMemorySize, SMEM_BYTES);
    dim3 grid(PANELS, BB);                    // 128 blocks, 1 per SM
    chamfer_mma<<<grid, TPB, SMEM_BYTES>>>(p, q);
    finalize1<<<BB, 256>>>(q);
    finalize2<<<1, 128>>>(out);
}

// round 6
// speedup vs baseline: 1.3265x; 1.0908x over previous
#include <cuda_runtime.h>
#include <cuda_bf16.h>
#include <cstdint>

// p, q: (B=64, N=2048, D=4) fp32 -> scalar chamfer + jet loss.
// One bf16 m16n8k16 MMA per 16x8 tile computes the EXACT (hi+lo)x(hi'+lo')
// product via K-slot layout: A=[h,l interleave | half-swapped], B=[h,l | repeat].
#define BB       64
#define NN       2048
#define TPB      256
#define NWARP    8
#define PROWS    128
#define PANELS   (NN / PROWS)        // 16
#define NBLK     (BB * PANELS)       // 1024 blocks
#define ITILES   (PROWS / 16)        // 8
#define NPASS    4
#define JT_PASS  8                   // j-tiles per warp per pass; 4*8*8=256=NN/8
#define FINF     __int_as_float(0x7f800000)

__device__ float  g_colmin[NBLK * NN];   // per-panel col-min partials
__device__ float  g_cham[NBLK];
__device__ float4 g_jetp[NBLK];
__device__ float4 g_jetq[BB];
__device__ float  g_batch[BB];

// hi/lo bf16 split packed in one u32 (low half = hi term = even K slot)
__device__ __forceinline__ unsigned split_bf16(float v) {
    unsigned short h = __bfloat16_as_ushort(__float2bfloat16_rn(v));
    float fh = __bfloat162float(__ushort_as_bfloat16(h));
    unsigned short l = __bfloat16_as_ushort(__float2bfloat16_rn(v - fh));
    return ((unsigned)l << 16) | (unsigned)h;
}
// monotone float<->uint mapping for shared atomicMin on floats
__device__ __forceinline__ unsigned fkey(float f) {
    unsigned u = __float_as_uint(f);
    return (u & 0x80000000u) ? ~u : (u | 0x80000000u);
}
__device__ __forceinline__ float fdecode(unsigned k) {
    return __uint_as_float((k & 0x80000000u) ? (k ^ 0x80000000u) : ~k);
}
__device__ __forceinline__ void mma_bf16(
    float& d0, float& d1, float& d2, float& d3,
    unsigned a0, unsigned a1, unsigned a2, unsigned a3, unsigned b0)
{
    asm volatile(
        "mma.sync.aligned.m16n8k16.row.col.f32.bf16.bf16.f32 "
        "{%0,%1,%2,%3}, {%4,%5,%6,%7}, {%8,%9}, {%10,%11,%12,%13};\n"
        : "=f"(d0), "=f"(d1), "=f"(d2), "=f"(d3)
        : "r"(a0), "r"(a1), "r"(a2), "r"(a3), "r"(b0), "r"(b0),
          "f"(0.f), "f"(0.f), "f"(0.f), "f"(0.f));
}
__device__ __forceinline__ float4 warp_sum4(float4 v) {
    #pragma unroll
    for (int off = 16; off > 0; off >>= 1) {
        v.x += __shfl_down_sync(0xffffffffu, v.x, off);
        v.y += __shfl_down_sync(0xffffffffu, v.y, off);
        v.z += __shfl_down_sync(0xffffffffu, v.z, off);
        v.w += __shfl_down_sync(0xffffffffu, v.w, off);
    }
    return v;
}

__global__ __launch_bounds__(TPB, 4) void chamfer_bf16(
    const float4* __restrict__ p, const float4* __restrict__ q)
{
    __shared__ __align__(16) unsigned sA[PROWS * 4];    // -2p, hi/lo bf16x2 per comp
    __shared__ __align__(16) unsigned sB[NN * 4];       // q,   hi/lo bf16x2 per comp
    __shared__ __align__(16) float    sQsq[NN];
    __shared__ __align__(16) float    sPsq[PROWS];
    __shared__ __align__(16) unsigned sRowMin[PROWS];
    __shared__ float4 sScr[2 * NWARP];
    __shared__ float  sRed[NWARP];

    const int panel = blockIdx.x, b = blockIdx.y, blk = b * PANELS + panel;
    const int tid = threadIdx.x, w = tid >> 5, lane = tid & 31;
    const int g = lane >> 2, t4 = lane & 3;

    // ---- staging ----
    float4 jp = make_float4(0.f, 0.f, 0.f, 0.f);
    if (tid < PROWS) {
        const float4 a = p[b * NN + panel * PROWS + tid];
        jp = a;
        sPsq[tid] = a.x * a.x + a.y * a.y + a.z * a.z + a.w * a.w;
        sA[tid * 4 + 0] = split_bf16(-2.f * a.x);
        sA[tid * 4 + 1] = split_bf16(-2.f * a.y);
        sA[tid * 4 + 2] = split_bf16(-2.f * a.z);
        sA[tid * 4 + 3] = split_bf16(-2.f * a.w);
        sRowMin[tid] = 0xFFFFFFFFu;
    }
    float4 jq = make_float4(0.f, 0.f, 0.f, 0.f);
    for (int j = tid; j < NN; j += TPB) {
        const float4 v = q[b * NN + j];
        jq.x += v.x; jq.y += v.y; jq.z += v.z; jq.w += v.w;
        sQsq[j] = v.x * v.x + v.y * v.y + v.z * v.z + v.w * v.w;
        sB[j * 4 + 0] = split_bf16(v.x);
        sB[j * 4 + 1] = split_bf16(v.y);
        sB[j * 4 + 2] = split_bf16(v.z);
        sB[j * 4 + 3] = split_bf16(v.w);
    }
    jp = warp_sum4(jp); jq = warp_sum4(jq);
    if (lane == 0) { sScr[w] = jp; sScr[NWARP + w] = jq; }
    __syncthreads();
    if (tid == 0) {
        float4 sp = sScr[0], sq = sScr[NWARP];
        #pragma unroll
        for (int k = 1; k < NWARP; k++) {
            sp.x += sScr[k].x; sp.y += sScr[k].y; sp.z += sScr[k].z; sp.w += sScr[k].w;
            sq.x += sScr[NWARP + k].x; sq.y += sScr[NWARP + k].y;
            sq.z += sScr[NWARP + k].z; sq.w += sScr[NWARP + k].w;
        }
        g_jetp[blk] = sp;
        if (panel == 0) g_jetq[b] = sq;   // every block sums full q; keep one
    }
    __syncthreads();

    // ---- main sweep ----
    for (int ps = 0; ps < NPASS; ps++) {
        const int jtbase = ps * (NWARP * JT_PASS) + w * JT_PASS;
        float colA[JT_PASS], colB[JT_PASS];
        #pragma unroll
        for (int jj = 0; jj < JT_PASS; jj++) { colA[jj] = FINF; colB[jj] = FINF; }

        for (int it = 0; it < ITILES; it++) {
            const int r0 = it * 16 + g;
            const unsigned a0 = sA[r0 * 4 + t4];
            const unsigned a1 = sA[(r0 + 8) * 4 + t4];
            const unsigned a2 = __funnelshift_l(a0, a0, 16);   // half-swapped K region
            const unsigned a3 = __funnelshift_l(a1, a1, 16);
            const float psq0 = sPsq[r0], psq1 = sPsq[r0 + 8];
            float rA0 = FINF, rB0 = FINF, rA1 = FINF, rB1 = FINF;

            #pragma unroll
            for (int jj = 0; jj < JT_PASS; jj++) {
                const int n8 = (jtbase + jj) * 8;
                const unsigned b0 = sB[(n8 + g) * 4 + t4];
                const float2 qq = *reinterpret_cast<const float2*>(&sQsq[n8 + 2 * t4]);
                float d0, d1, d2, d3;                 // d = -2 p.q (exact)
                mma_bf16(d0, d1, d2, d3, a0, a1, a2, a3, b0);
                rA0 = fminf(rA0, d0 + qq.x); rB0 = fminf(rB0, d1 + qq.y);
                rA1 = fminf(rA1, d2 + qq.x); rB1 = fminf(rB1, d3 + qq.y);
                colA[jj] = fminf(colA[jj], fminf(d0 + psq0, d2 + psq1));
                colB[jj] = fminf(colB[jj], fminf(d1 + psq0, d3 + psq1));
            }
            // fold this i-tile's row mins into shared (min over the 8 cols held
            // by the t4 quad, then one atomic per row)
            float m0 = fminf(rA0, rB0), m1 = fminf(rA1, rB1);
            m0 = fminf(m0, __shfl_xor_sync(0xffffffffu, m0, 1));
            m0 = fminf(m0, __shfl_xor_sync(0xffffffffu, m0, 2));
            m1 = fminf(m1, __shfl_xor_sync(0xffffffffu, m1, 1));
            m1 = fminf(m1, __shfl_xor_sync(0xffffffffu, m1, 2));
            if (t4 == 0) {
                atomicMin(&sRowMin[r0], fkey(m0));
                atomicMin(&sRowMin[r0 + 8], fkey(m1));
            }
        }
        // col writeout for this pass (reduce over g lanes)
        #pragma unroll
        for (int jj = 0; jj < JT_PASS; jj++) {
            float c0 = colA[jj], c1 = colB[jj];
            c0 = fminf(c0, __shfl_xor_sync(0xffffffffu, c0, 4));
            c0 = fminf(c0, __shfl_xor_sync(0xffffffffu, c0, 8));
            c0 = fminf(c0, __shfl_xor_sync(0xffffffffu, c0, 16));
            c1 = fminf(c1, __shfl_xor_sync(0xffffffffu, c1, 4));
            c1 = fminf(c1, __shfl_xor_sync(0xffffffffu, c1, 8));
            c1 = fminf(c1, __shfl_xor_sync(0xffffffffu, c1, 16));
            if (g == 0) {
                const int col = (jtbase + jj) * 8 + 2 * t4;
                *reinterpret_cast<float2*>(&g_colmin[blk * NN + col]) =
                    make_float2(c0, c1);
            }
        }
    }

    // ---- row-side block sum: psq + decoded row-min ----
    __syncthreads();
    float local = (tid < PROWS) ? (sPsq[tid] + fdecode(sRowMin[tid])) : 0.f;
    #pragma unroll
    for (int off = 16; off > 0; off >>= 1)
        local += __shfl_down_sync(0xffffffffu, local, off);
    if (lane == 0) sRed[w] = local;
    __syncthreads();
    if (tid == 0) {
        float s = 0.f;
        #pragma unroll
        for (int k = 0; k < NWARP; k++) s += sRed[k];
        g_cham[blk] = s;
    }
}

// Per batch: col-side sum (min over 16 panels + qsq) + jet term.
__global__ __launch_bounds__(256) void finalize1(const float4* __restrict__ q)
{
    const int b = blockIdx.x, tid = threadIdx.x;
    float local = 0.f;
    for (int j = tid; j < NN; j += 256) {
        float m = g_colmin[(b * PANELS + 0) * NN + j];
        #pragma unroll
        for (int pn = 1; pn < PANELS; pn++)
            m = fminf(m, g_colmin[(b * PANELS + pn) * NN + j]);
        const float4 v = q[b * NN + j];
        local += v.x * v.x + v.y * v.y + v.z * v.z + v.w * v.w + m;
    }
    if (tid == 0) {
        float4 sp = g_jetp[b * PANELS];
        #pragma unroll
        for (int pn = 1; pn < PANELS; pn++) {
            const float4 t = g_jetp[b * PANELS + pn];
            sp.x += t.x; sp.y += t.y; sp.z += t.z; sp.w += t.w;
        }
        const float4 sq = g_jetq[b];
        const float dx = sp.x - sq.x, dy = sp.y - sq.y;
        const float dz = sp.z - sq.z, dw = sp.w - sq.w;
        local += dx * dx + dy * dy + dz * dz + dw * dw;
    }
    __shared__ float sh[256];
    sh[tid] = local;
    __syncthreads();
    #pragma unroll
    for (int off = 128; off > 0; off >>= 1) {
        if (tid < off) sh[tid] += sh[tid + off];
        __syncthreads();
    }
    if (tid == 0) g_batch[b] = sh[0];
}

__global__ __launch_bounds__(128) void finalize2(float* __restrict__ out)
{
    const int tid = threadIdx.x;
    float v = 0.f;
    for (int i = tid; i < BB; i += 128)   v += g_batch[i];
    for (int i = tid; i < NBLK; i += 128) v += g_cham[i];
    __shared__ float sh[128];
    sh[tid] = v;
    __syncthreads();
    #pragma unroll
    for (int off = 64; off > 0; off >>= 1) {
        if (tid < off) sh[tid] += sh[tid + off];
        __syncthreads();
    }
    if (tid == 0) out[0] = sh[0];
}

extern "C" void kernel_launch(void* const* d_in, const int* in_sizes, int n_in,
                              void* d_out, int out_size)
{
    const float4* p = (const float4*)d_in[0];
    const float4* q = (const float4*)d_in[1];
    float* out = (float*)d_out;

    dim3 grid(PANELS, BB);                    // 1024 blocks, 4/SM, ~2% tail
    chamfer_bf16<<<grid, TPB>>>(p, q);
    finalize1<<<BB, 256>>>(q);
    finalize2<<<1, 128>>>(out);
}